// round 13
// baseline (speedup 1.0000x reference)
#include <cuda_runtime.h>
#include <cuda_fp16.h>
#include <math.h>
#include <stdint.h>

#define NN 40000
#define EE 320000
#define DD 128
#define HH 4
#define TT 3
#define RR 5
#define KKM 3
#define DKK 32
#define ND (NN*DD)
#define MSZ (DD*DD)
#define NPART 157
#define INV_SQRT_DK 0.17677669529663687f   // 1/sqrt(32)

// GEMM smem (bytes): A full-K 128 rows x 272B x 2 planes at 0 / 34816.
// B: double-buffered 32-k stages: buf b at 69632 + b*17408, planes +8704.
#define M_AL 34816
#define M_B  69632
#define GSM_MS 104448
#define NW 18   // weight slots: 0-2 qw, 3-5 kw, 6-8 vw, 9-11 aw, 12-14 WMk, 15-17 Wf2

// ---------------- scratch (device globals; no allocation allowed) -------------
__device__ float    g_q[ND];
__device__ float    g_k[ND];
__device__ float    g_v[ND];
__device__ float    g_qA[NN*RR*DD];
__device__ float    g_logits[EE*HH];     // exp(logit)
__device__ float    g_sum[NN*HH];
__device__ int      g_deg[NN];
__device__ float    g_aggm[KKM*ND];
__device__ float    g_front2[KKM*ND];    // x @ Wf2_k + bf2_k
__device__ float    g_trans[ND];
__device__ float    g_Wf[KKM*MSZ];       // Wq @ Wak[k]          (fp32 exact)
__device__ float    g_Wf2[KKM*MSZ];      // Wf[k] @ Wkl^T        (fp32 exact)
__device__ float    g_bf[KKM*DD];        // bq @ Wak[k]
__device__ float    g_bf2[KKM*DD];       // bf[k] @ Wkl^T
__device__ float    g_e[KKM*DD];         // Wf[k] @ bkl
__device__ float    g_c[KKM];            // bf[k] . bkl
// presplit half planes
__device__ __half   g_xh[ND],        g_xl[ND];
__device__ __half   g_aggh[KKM*ND],  g_aggl[KKM*ND];
__device__ __half   g_resh[ND],      g_resl[ND];
__device__ __half   g_w2[NW*2*MSZ];      // weights: slot*2*MSZ, hi then lo plane
__device__ int      g_list[TT*NN];
__device__ int      g_cnt[TT];
__device__ int      g_cur[TT];

// ---------------- helpers ----------------
__device__ __forceinline__ float signed_cbrt(float a) {
    float s = (a > 0.f) ? 1.f : ((a < 0.f) ? -1.f : 0.f);
    return s * cbrtf(fabsf(a) + 1e-18f);
}
__device__ __forceinline__ float gelu_exact(float x) {
    return 0.5f * x * (1.f + erff(x * 0.70710678118654752440f));
}
__device__ __forceinline__ float warp_sum(float p) {
    #pragma unroll
    for (int o = 16; o > 0; o >>= 1) p += __shfl_xor_sync(0xffffffffu, p, o);
    return p;
}
__device__ __forceinline__ void splith(float x, __half& hi, __half& lo) {
    __half h = __float2half_rn(x);
    hi = h;
    lo = __float2half_rn(x - __half2float(h));
}
__device__ __forceinline__ uint32_t smem_u32(const void* p) {
    uint32_t a;
    asm("{ .reg .u64 t; cvta.to.shared.u64 t, %1; cvt.u32.u64 %0, t; }" : "=r"(a) : "l"(p));
    return a;
}

#define CPA16(dst, src, sz)                                                   \
    asm volatile("cp.async.ca.shared.global [%0], [%1], 16, %2;"              \
        :: "r"(dst), "l"(src), "r"(sz))
#define CPA_COMMIT() asm volatile("cp.async.commit_group;" ::: "memory")
#define CPA_WAIT1()  asm volatile("cp.async.wait_group 1;" ::: "memory")
#define LDSM4(r, addr)                                                        \
    asm volatile("ldmatrix.sync.aligned.m8n8.x4.shared.b16 {%0,%1,%2,%3}, [%4];" \
        : "=r"((r)[0]), "=r"((r)[1]), "=r"((r)[2]), "=r"((r)[3]) : "r"(addr))
#define LDSM4T(r, addr)                                                       \
    asm volatile("ldmatrix.sync.aligned.m8n8.x4.trans.shared.b16 {%0,%1,%2,%3}, [%4];" \
        : "=r"((r)[0]), "=r"((r)[1]), "=r"((r)[2]), "=r"((r)[3]) : "r"(addr))
#define MMA16(acc, a, b0, b1)                                                 \
    asm volatile("mma.sync.aligned.m16n8k16.row.col.f32.f16.f16.f32 "         \
        "{%0,%1,%2,%3}, {%4,%5,%6,%7}, {%8,%9}, {%0,%1,%2,%3};"               \
        : "+f"((acc)[0]), "+f"((acc)[1]), "+f"((acc)[2]), "+f"((acc)[3])      \
        : "r"((a)[0]), "r"((a)[1]), "r"((a)[2]), "r"((a)[3]), "r"(b0), "r"(b1))

// ------ wcomb1: Wf[k] = Wq @ Wak[k]; y==3: bf + counter resets ---------------
__global__ void wcomb1(const float* __restrict__ Wq, const float* __restrict__ Wak,
                       const float* __restrict__ bq) {
    int y = blockIdx.y;
    if (y == 3) {
        if (blockIdx.x) return;
        if (threadIdx.x < TT) {
            g_cnt[threadIdx.x] = 0;
            g_cur[threadIdx.x] = threadIdx.x * NN;
        }
        for (int idx = threadIdx.x; idx < KKM * DD; idx += blockDim.x) {
            int k = idx >> 7, n = idx & 127;
            float s = 0.f;
            for (int d = 0; d < DD; d++) s += bq[d] * Wak[((long long)k * DD + d) * DD + n];
            g_bf[idx] = s;
        }
        return;
    }
    const float* A = Wq;
    const float* Bm = Wak + (long long)y * MSZ;
    float* C = g_Wf + (long long)y * MSZ;
    int bm = blockIdx.x * 64;
    __shared__ float Xs[64][8];
    __shared__ float Ws[8][128];
    int tid = threadIdx.x, ty = tid >> 5, tx = tid & 31;
    float acc[8][4];
    #pragma unroll
    for (int i = 0; i < 8; i++)
        #pragma unroll
        for (int j = 0; j < 4; j++) acc[i][j] = 0.f;
    for (int kb = 0; kb < 16; kb++) {
        {
            int m = tid >> 2, kq = (tid & 3) << 1;
            float2 xv = *(const float2*)(A + (long long)(bm + m) * DD + kb * 8 + kq);
            Xs[m][kq] = xv.x; Xs[m][kq + 1] = xv.y;
            int kk = tid >> 5, c4 = (tid & 31) << 2;
            *(float4*)&Ws[kk][c4] = *(const float4*)(Bm + (long long)(kb * 8 + kk) * DD + c4);
        }
        __syncthreads();
        #pragma unroll
        for (int kk = 0; kk < 8; kk++) {
            float4 b = *(float4*)&Ws[kk][tx << 2];
            #pragma unroll
            for (int i = 0; i < 8; i++) {
                float a = Xs[ty * 8 + i][kk];
                acc[i][0] += a * b.x; acc[i][1] += a * b.y;
                acc[i][2] += a * b.z; acc[i][3] += a * b.w;
            }
        }
        __syncthreads();
    }
    #pragma unroll
    for (int i = 0; i < 8; i++) {
        float4 o;
        o.x = acc[i][0]; o.y = acc[i][1]; o.z = acc[i][2]; o.w = acc[i][3];
        *(float4*)(C + (long long)(bm + ty * 8 + i) * DD + (tx << 2)) = o;
    }
}

// ------ wcomb2: Wf2[k] = Wf[k] @ Wkl^T; y==3: bf2, e, c ----------------------
__global__ void wcomb2(const float* __restrict__ Wkl, const float* __restrict__ bkl) {
    int y = blockIdx.y;
    if (y == 3) {
        if (blockIdx.x) return;
        for (int idx = threadIdx.x; idx < KKM * DD; idx += blockDim.x) {
            int k = idx >> 7, j = idx & 127;
            float s = 0.f, s2 = 0.f;
            const float* bfk = g_bf + k * DD;
            const float* wr = Wkl + (long long)j * DD;          // Wkl row j
            const float* wfr = g_Wf + ((long long)k * DD + j) * DD;  // Wf[k] row j
            for (int d = 0; d < DD; d++) {
                s  += bfk[d] * wr[d];     // bf2
                s2 += wfr[d] * bkl[d];    // e
            }
            g_bf2[idx] = s;
            g_e[idx] = s2;
        }
        if (threadIdx.x < KKM) {
            int k = threadIdx.x;
            float s = 0.f;
            for (int d = 0; d < DD; d++) s += g_bf[k * DD + d] * bkl[d];
            g_c[k] = s;
        }
        return;
    }
    const float* A = g_Wf + (long long)y * MSZ;
    float* C = g_Wf2 + (long long)y * MSZ;
    int bm = blockIdx.x * 64;
    __shared__ float Xs[64][8];
    __shared__ float Ws[8][128];
    int tid = threadIdx.x, ty = tid >> 5, tx = tid & 31;
    float acc[8][4];
    #pragma unroll
    for (int i = 0; i < 8; i++)
        #pragma unroll
        for (int j = 0; j < 4; j++) acc[i][j] = 0.f;
    for (int kb = 0; kb < 16; kb++) {
        {
            int m = tid >> 2, kq = (tid & 3) << 1;
            float2 xv = *(const float2*)(A + (long long)(bm + m) * DD + kb * 8 + kq);
            Xs[m][kq] = xv.x; Xs[m][kq + 1] = xv.y;
            // transposed B: Ws[kk][c] = Wkl[c*DD + kb*8+kk]
            int kk = tid >> 5, c4 = (tid & 31) << 2;
            #pragma unroll
            for (int j = 0; j < 4; j++)
                Ws[kk][c4 + j] = Wkl[(long long)(c4 + j) * DD + kb * 8 + kk];
        }
        __syncthreads();
        #pragma unroll
        for (int kk = 0; kk < 8; kk++) {
            float4 b = *(float4*)&Ws[kk][tx << 2];
            #pragma unroll
            for (int i = 0; i < 8; i++) {
                float a = Xs[ty * 8 + i][kk];
                acc[i][0] += a * b.x; acc[i][1] += a * b.y;
                acc[i][2] += a * b.z; acc[i][3] += a * b.w;
            }
        }
        __syncthreads();
    }
    #pragma unroll
    for (int i = 0; i < 8; i++) {
        float4 o;
        o.x = acc[i][0]; o.y = acc[i][1]; o.z = acc[i][2]; o.w = acc[i][3];
        *(float4*)(C + (long long)(bm + ty * 8 + i) * DD + (tx << 2)) = o;
    }
}

// ------- presplit everything + zero softmax state + fused scatter ------------
__global__ void k_splitall(const float* __restrict__ x,
                           const float* __restrict__ qw, const float* __restrict__ kw,
                           const float* __restrict__ vw, const float* __restrict__ aw,
                           const float* __restrict__ WMk, const int* __restrict__ nt) {
    // fused segmented scatter in the first NPART blocks
    if (blockIdx.x < NPART) {
        __shared__ int h[TT], base[TT];
        if (threadIdx.x < TT) h[threadIdx.x] = 0;
        __syncthreads();
        int n = blockIdx.x * blockDim.x + threadIdx.x;
        int t = 0, loc = 0;
        bool v = (n < NN);
        if (v) { t = nt[n]; loc = atomicAdd(&h[t], 1); }
        __syncthreads();
        if (threadIdx.x < TT && h[threadIdx.x]) {
            base[threadIdx.x] = atomicAdd(&g_cur[threadIdx.x], h[threadIdx.x]);
            atomicAdd(&g_cnt[threadIdx.x], h[threadIdx.x]);
        }
        __syncthreads();
        if (v) g_list[base[t] + loc] = n;
    }

    long long total = (long long)ND + (long long)NW * MSZ;
    long long i = (long long)blockIdx.x * blockDim.x + threadIdx.x;
    if (i >= total) return;
    if (i < NN * HH) g_sum[i] = 0.f;
    if (i < NN) g_deg[i] = 0;
    float s;
    __half h, l;
    if (i < ND) {
        s = x[i];
        splith(s, h, l);
        g_xh[i] = h; g_xl[i] = l;
    } else {
        long long wi = i - ND;
        if      (wi <  3LL * MSZ) s = qw[wi];
        else if (wi <  6LL * MSZ) s = kw[wi - 3LL * MSZ];
        else if (wi <  9LL * MSZ) s = vw[wi - 6LL * MSZ];
        else if (wi < 12LL * MSZ) s = aw[wi - 9LL * MSZ];
        else if (wi < 15LL * MSZ) s = WMk[wi - 12LL * MSZ];
        else                      s = g_Wf2[wi - 15LL * MSZ];
        splith(s, h, l);
        long long slot = wi >> 14;              // /MSZ
        long long off  = wi & (MSZ - 1);
        g_w2[slot * 2 * MSZ + off] = h;
        g_w2[slot * 2 * MSZ + MSZ + off] = l;
    }
}

// ------ multi-set fp16-split tensor GEMM, hoisted staging addresses ----------
struct GMSet {
    int wslot;
    int waddgy;
    const float* bias;
    int baddgy;
    float* out;
    long long ogys;
};
struct GMArgs { GMSet s[6]; int n; };

__global__ __launch_bounds__(256, 2) void tc_gemm_ms(
    const __half* __restrict__ Xh, const __half* __restrict__ Xl, long long xgys,
    int typed, int nrows, GMArgs args)
{
    extern __shared__ char smc[];
    uint32_t sb = smem_u32(smc);

    int gy = blockIdx.y;
    const int* rows = nullptr;
    int cnt;
    if (typed) {
        rows = g_list + (long long)gy * NN;
        cnt = g_cnt[gy];
    } else {
        Xh += (long long)gy * xgys;
        Xl += (long long)gy * xgys;
        cnt = nrows;
    }
    int bm = blockIdx.x * 128;
    if (bm >= cnt) return;

    int tid = threadIdx.x, wid = tid >> 5, lane = tid & 31;
    int warpM = wid & 3, warpN = wid >> 2;
    int rbase = warpM * 32, cbase = warpN * 64;
    int qid = lane >> 2, tq = lane & 3;

    int li = lane & 7, ls = lane >> 3;
    int a_row = li + ((ls & 1) << 3);
    int a_col = ((ls >> 1) & 1) << 3;
    int b_krow = li + ((ls >> 1) << 3);
    int b_ncol = (ls & 1) << 3;

    uint32_t aoff = sb + (uint32_t)(rbase + a_row) * 272u + (uint32_t)a_col * 2u;
    uint32_t bfrag = (uint32_t)b_krow * 272u + (uint32_t)(cbase + b_ncol) * 2u;

    // hoisted B-staging offsets (4 chunks/thread)
    int bSrc[4]; uint32_t bDst[4];
    #pragma unroll
    for (int it = 0; it < 4; it++) {
        int s = tid + it * 256;
        int plane = s >> 9, rc = s & 511;
        int k = rc >> 4, c16 = rc & 15;
        bSrc[it] = plane * MSZ + k * DD + c16 * 8;
        bDst[it] = (uint32_t)(plane * 8704 + k * 272 + c16 * 16);
    }
    uint32_t bB0 = sb + M_B, bB1 = sb + M_B + 17408u;

    // stage full-K A (once)
    #pragma unroll
    for (int it = 0; it < 16; it++) {
        int s = tid + it * 256;
        int plane = s >> 11, rc = s & 2047;
        int r = rc >> 4, c16 = rc & 15;
        int gr = bm + r;
        int row = (gr < cnt) ? (rows ? rows[gr] : gr) : 0;
        unsigned sz = (gr < cnt) ? 16u : 0u;
        const __half* srcp = (plane ? Xl : Xh) + (long long)row * DD + c16 * 8;
        uint32_t dst = sb + (plane ? M_AL : 0) + (uint32_t)r * 272u + (uint32_t)c16 * 16u;
        CPA16(dst, srcp, sz);
    }
    // B stage 0 of set 0
    {
        int slot0 = args.s[0].wslot + (args.s[0].waddgy ? gy : 0);
        const __half* wb = g_w2 + (long long)slot0 * (2 * MSZ);
        #pragma unroll
        for (int it = 0; it < 4; it++) CPA16(bB0 + bDst[it], wb + bSrc[it], 16u);
    }
    CPA_COMMIT();

    int gst = 0;
    int nstages = args.n * 4;

    for (int si = 0; si < args.n; si++) {
        float acc[2][8][4];
        #pragma unroll
        for (int mi = 0; mi < 2; mi++)
            #pragma unroll
            for (int ni = 0; ni < 8; ni++)
                #pragma unroll
                for (int j = 0; j < 4; j++) acc[mi][ni][j] = 0.f;

        for (int st = 0; st < 4; st++) {
            int nb = gst + 1;
            if (nb < nstages) {
                int nsi = nb >> 2, nst = nb & 3;
                int nslot = args.s[nsi].wslot + (args.s[nsi].waddgy ? gy : 0);
                const __half* wb = g_w2 + (long long)nslot * (2 * MSZ) + nst * (32 * DD);
                uint32_t bb = (nb & 1) ? bB1 : bB0;
                #pragma unroll
                for (int it = 0; it < 4; it++) CPA16(bb + bDst[it], wb + bSrc[it], 16u);
            }
            CPA_COMMIT();
            CPA_WAIT1();
            __syncthreads();

            uint32_t bbase = (gst & 1) ? bB1 : bB0;
            #pragma unroll
            for (int k16 = 0; k16 < 2; k16++) {
                uint32_t ka = aoff + (uint32_t)(st * 64 + k16 * 32);
                uint32_t ah[2][4], al[2][4];
                LDSM4(ah[0], ka);
                LDSM4(ah[1], ka + 16u * 272u);
                LDSM4(al[0], ka + (uint32_t)M_AL);
                LDSM4(al[1], ka + (uint32_t)M_AL + 16u * 272u);
                #pragma unroll
                for (int nf = 0; nf < 4; nf++) {
                    uint32_t kb = bbase + bfrag + (uint32_t)k16 * 4352u + (uint32_t)nf * 32u;
                    uint32_t bhf[4], blf[4];
                    LDSM4T(bhf, kb);
                    LDSM4T(blf, kb + 8704u);
                    #pragma unroll
                    for (int j = 0; j < 2; j++) {
                        #pragma unroll
                        for (int mi = 0; mi < 2; mi++) {
                            float* a4 = acc[mi][nf * 2 + j];
                            MMA16(a4, ah[mi], bhf[j], bhf[2 + j]);
                            MMA16(a4, al[mi], bhf[j], bhf[2 + j]);
                            MMA16(a4, ah[mi], blf[j], blf[2 + j]);
                        }
                    }
                }
            }
            __syncthreads();
            gst++;
        }

        const GMSet& st_ = args.s[si];
        const float* bp = st_.bias;
        if (bp && st_.baddgy) bp += (long long)gy * DD;
        float* op = st_.out + (long long)gy * st_.ogys;
        #pragma unroll
        for (int ni = 0; ni < 8; ni++) {
            int col = cbase + ni * 8 + tq * 2;
            float bx = bp ? __ldg(bp + col) : 0.f;
            float by = bp ? __ldg(bp + col + 1) : 0.f;
            #pragma unroll
            for (int mi = 0; mi < 2; mi++) {
                int r0 = bm + rbase + mi * 16 + qid;
                if (r0 < cnt) {
                    int row = rows ? rows[r0] : r0;
                    float2 o = make_float2(acc[mi][ni][0] + bx, acc[mi][ni][1] + by);
                    *(float2*)(op + (long long)row * DD + col) = o;
                }
                int r1 = r0 + 8;
                if (r1 < cnt) {
                    int row = rows ? rows[r1] : r1;
                    float2 o = make_float2(acc[mi][ni][2] + bx, acc[mi][ni][3] + by);
                    *(float2*)(op + (long long)row * DD + col) = o;
                }
            }
        }
    }
}

// ---------------- qA = rel_att-transformed q ----------------------------------
__global__ void k_qA(const float* __restrict__ rel_att) {
    extern __shared__ float Ashm[];
    for (int i = threadIdx.x; i < RR * HH * DKK * DKK; i += blockDim.x) {
        int rh = i >> 10, dm = i & 1023, d = dm >> 5, m = dm & 31;
        Ashm[(rh * 32 + m) * 32 + d] = rel_att[i];
    }
    __syncthreads();
    int lane = threadIdx.x & 31;
    int gw = (blockIdx.x * blockDim.x + threadIdx.x) >> 5;
    int nw = (gridDim.x * blockDim.x) >> 5;
    for (int n = gw; n < NN; n += nw) {
        float qr[HH];
        #pragma unroll
        for (int h = 0; h < HH; h++) qr[h] = g_q[n * DD + h * 32 + lane];
        #pragma unroll
        for (int h = 0; h < HH; h++) {
            float a0 = 0, a1 = 0, a2 = 0, a3 = 0, a4 = 0;
            #pragma unroll
            for (int m = 0; m < 32; m++) {
                float qm = __shfl_sync(0xffffffffu, qr[h], m);
                int base = (h * 32 + m) * 32 + lane;
                a0 += Ashm[base        ] * qm;
                a1 += Ashm[base +  4096] * qm;
                a2 += Ashm[base +  8192] * qm;
                a3 += Ashm[base + 12288] * qm;
                a4 += Ashm[base + 16384] * qm;
            }
            g_qA[((n * RR + 0) * HH + h) * 32 + lane] = a0;
            g_qA[((n * RR + 1) * HH + h) * 32 + lane] = a1;
            g_qA[((n * RR + 2) * HH + h) * 32 + lane] = a2;
            g_qA[((n * RR + 3) * HH + h) * 32 + lane] = a3;
            g_qA[((n * RR + 4) * HH + h) * 32 + lane] = a4;
        }
    }
}

// ---- edge logits + fused exp + segment sum + degree (no max pass) -----------
__global__ void k_logits(const int* __restrict__ ei, const int* __restrict__ et,
                         const float* __restrict__ rel_pri) {
    int lane = threadIdx.x & 31;
    int gw = (blockIdx.x * blockDim.x + threadIdx.x) >> 5;
    int nw = (gridDim.x * blockDim.x) >> 5;
    for (int e = gw; e < EE; e += nw) {
        int s = ei[e], tg = ei[EE + e], r = et[e];
        float p0, p1, p2, p3;
        {
            const float* kb = g_k + (long long)s * DD;
            const float* qa = g_qA + ((long long)tg * RR + r) * DD;
            p0 = kb[lane]      * qa[lane];
            p1 = kb[32 + lane] * qa[32 + lane];
            p2 = kb[64 + lane] * qa[64 + lane];
            p3 = kb[96 + lane] * qa[96 + lane];
        }
        p0 = warp_sum(p0); p1 = warp_sum(p1); p2 = warp_sum(p2); p3 = warp_sum(p3);
        if (lane == 0) {
            atomicAdd(&g_deg[tg], 1);
            float e0 = expf(p0 * rel_pri[r * HH + 0] * INV_SQRT_DK);
            float e1 = expf(p1 * rel_pri[r * HH + 1] * INV_SQRT_DK);
            float e2 = expf(p2 * rel_pri[r * HH + 2] * INV_SQRT_DK);
            float e3 = expf(p3 * rel_pri[r * HH + 3] * INV_SQRT_DK);
            g_logits[e * HH + 0] = e0; g_logits[e * HH + 1] = e1;
            g_logits[e * HH + 2] = e2; g_logits[e * HH + 3] = e3;
            atomicAdd(&g_sum[tg * HH + 0], e0);
            atomicAdd(&g_sum[tg * HH + 1], e1);
            atomicAdd(&g_sum[tg * HH + 2], e2);
            atomicAdd(&g_sum[tg * HH + 3], e3);
        }
    }
}

// ------- messages / agg (edge n < N shortcut); writes SPLIT halves -----------
__global__ void k_msg(const float* __restrict__ rel_msg, const int* __restrict__ ei,
                      const int* __restrict__ et) {
    extern __shared__ float Ms[];
    for (int i = threadIdx.x; i < RR * HH * DKK * DKK; i += blockDim.x) Ms[i] = rel_msg[i];
    __syncthreads();
    int lane = threadIdx.x & 31;
    int gw = (blockIdx.x * blockDim.x + threadIdx.x) >> 5;
    int nw = (gridDim.x * blockDim.x) >> 5;
    for (int n = gw; n < NN; n += nw) {
        int s = ei[n], tg = ei[EE + n], r = et[n];
        float deg = (float)g_deg[n];
        float vr[HH];
        #pragma unroll
        for (int h = 0; h < HH; h++) vr[h] = g_v[(long long)s * DD + h * 32 + lane];
        #pragma unroll
        for (int h = 0; h < HH; h++) {
            float att = g_logits[n * HH + h] / (g_sum[tg * HH + h] + 1e-16f);
            float vp = 0.f;
            const float* Mb = Ms + (r * HH + h) * 1024;
            #pragma unroll
            for (int d = 0; d < 32; d++) {
                float vd = __shfl_sync(0xffffffffu, vr[h], d);
                vp += Mb[d * 32 + lane] * vd;
            }
            float base = deg * att;
            int o = n * DD + h * 32 + lane;
            float vp2 = vp * vp;
            float m1 = base * vp;
            float m2 = base * vp2;
            float m3 = signed_cbrt(base * vp2 * vp);
            __half hh, ll;
            splith(m1, hh, ll); g_aggh[o] = hh;          g_aggl[o] = ll;
            splith(m2, hh, ll); g_aggh[ND + o] = hh;     g_aggl[ND + o] = ll;
            splith(m3, hh, ll); g_aggh[2 * ND + o] = hh; g_aggl[2 * ND + o] = ll;
        }
    }
}

// -- gate = sigmoid(dot(front2,aggm) + dot(e_k,x) + c_k); res += gate*aggm ----
__global__ void k_gate(const float* __restrict__ x) {
    int w = (blockIdx.x * blockDim.x + threadIdx.x) >> 5;
    int lane = threadIdx.x & 31;
    if (w >= NN) return;
    int o = w * DD + lane * 4;
    float4 xv = *(const float4*)(x + o);
    float4 r4 = make_float4(0.f, 0.f, 0.f, 0.f);
    #pragma unroll
    for (int k = 0; k < KKM; k++) {
        float4 f = *(float4*)&g_front2[k * ND + o];
        float4 a = *(float4*)&g_aggm[k * ND + o];
        float4 ek = *(const float4*)&g_e[k * DD + lane * 4];
        float p = f.x * a.x + f.y * a.y + f.z * a.z + f.w * a.w
                + ek.x * xv.x + ek.y * xv.y + ek.z * xv.z + ek.w * xv.w;
        p = warp_sum(p);
        float gate = 1.f / (1.f + expf(-(p + g_c[k])));
        r4.x += gate * a.x; r4.y += gate * a.y; r4.z += gate * a.z; r4.w += gate * a.w;
    }
    float y0 = gelu_exact(r4.x), y1 = gelu_exact(r4.y);
    float y2 = gelu_exact(r4.z), y3 = gelu_exact(r4.w);
    __half h0, h1, h2, h3, l0, l1, l2, l3;
    splith(y0, h0, l0); splith(y1, h1, l1);
    splith(y2, h2, l2); splith(y3, h3, l3);
    *(__half2*)&g_resh[o]     = __halves2half2(h0, h1);
    *(__half2*)&g_resh[o + 2] = __halves2half2(h2, h3);
    *(__half2*)&g_resl[o]     = __halves2half2(l0, l1);
    *(__half2*)&g_resl[o + 2] = __halves2half2(l2, l3);
}

// ---------------- skip blend + LayerNorm --------------------------------------
__global__ void k_postln(const int* __restrict__ nt, const float* __restrict__ xin,
                         const float* __restrict__ skip, const float* __restrict__ lng,
                         const float* __restrict__ lnb, float* __restrict__ out) {
    int wid = (blockIdx.x * blockDim.x + threadIdx.x) >> 5;
    int lane = threadIdx.x & 31;
    if (wid >= NN) return;
    int t = nt[wid];
    float alpha = 1.f / (1.f + expf(-skip[t]));
    int o = wid * DD + lane * 4;
    float4 tr = *(float4*)&g_trans[o];
    float4 xv = *(const float4*)(xin + o);
    float y0 = tr.x * alpha + xv.x * (1.f - alpha);
    float y1 = tr.y * alpha + xv.y * (1.f - alpha);
    float y2 = tr.z * alpha + xv.z * (1.f - alpha);
    float y3 = tr.w * alpha + xv.w * (1.f - alpha);
    float s  = y0 + y1 + y2 + y3;
    float ss = y0 * y0 + y1 * y1 + y2 * y2 + y3 * y3;
    #pragma unroll
    for (int of = 16; of > 0; of >>= 1) {
        s  += __shfl_xor_sync(0xffffffffu, s,  of);
        ss += __shfl_xor_sync(0xffffffffu, ss, of);
    }
    float mu  = s * (1.f / 128.f);
    float inv = rsqrtf(ss * (1.f / 128.f) - mu * mu + 1e-5f);
    float4 gg = *(const float4*)(lng + t * DD + lane * 4);
    float4 bb = *(const float4*)(lnb + t * DD + lane * 4);
    float4 o4;
    o4.x = (y0 - mu) * inv * gg.x + bb.x;
    o4.y = (y1 - mu) * inv * gg.y + bb.y;
    o4.z = (y2 - mu) * inv * gg.z + bb.z;
    o4.w = (y3 - mu) * inv * gg.w + bb.w;
    *(float4*)(out + (long long)wid * DD + lane * 4) = o4;
}

// ---------------- launch ----------------
extern "C" void kernel_launch(void* const* d_in, const int* in_sizes, int n_in,
                              void* d_out, int out_size) {
    const float* meta_xs  = (const float*)d_in[0];
    const int*   node_type= (const int*)  d_in[1];
    const int*   edge_idx = (const int*)  d_in[2];
    const int*   edge_type= (const int*)  d_in[3];
    const float* q_w = (const float*)d_in[5],  *q_b = (const float*)d_in[6];
    const float* k_w = (const float*)d_in[7],  *k_b = (const float*)d_in[8];
    const float* v_w = (const float*)d_in[9],  *v_b = (const float*)d_in[10];
    const float* a_w = (const float*)d_in[11], *a_b = (const float*)d_in[12];
    const float* rel_pri = (const float*)d_in[13];
    const float* rel_att = (const float*)d_in[14];
    const float* rel_msg = (const float*)d_in[15];
    const float* WMk = (const float*)d_in[16];
    const float* Wak = (const float*)d_in[17];
    const float* Wq  = (const float*)d_in[18], *bq  = (const float*)d_in[19];
    const float* Wkl = (const float*)d_in[20], *bkl = (const float*)d_in[21];
    const float* skip= (const float*)d_in[22];
    const float* lng = (const float*)d_in[23], *lnb = (const float*)d_in[24];
    float* out = (float*)d_out;

    cudaFuncSetAttribute(k_qA,       cudaFuncAttributeMaxDynamicSharedMemorySize, 81920);
    cudaFuncSetAttribute(k_msg,      cudaFuncAttributeMaxDynamicSharedMemorySize, 81920);
    cudaFuncSetAttribute(tc_gemm_ms, cudaFuncAttributeMaxDynamicSharedMemorySize, GSM_MS);

    void *pq, *pk, *pv, *paggm, *pfront2, *ptrans, *pbf2;
    void *pxh, *pxl, *paggh, *paggl, *presh, *presl;
    cudaGetSymbolAddress(&pq, g_q);
    cudaGetSymbolAddress(&pk, g_k);
    cudaGetSymbolAddress(&pv, g_v);
    cudaGetSymbolAddress(&paggm, g_aggm);
    cudaGetSymbolAddress(&pfront2, g_front2);
    cudaGetSymbolAddress(&ptrans, g_trans);
    cudaGetSymbolAddress(&pbf2, g_bf2);
    cudaGetSymbolAddress(&pxh, g_xh);
    cudaGetSymbolAddress(&pxl, g_xl);
    cudaGetSymbolAddress(&paggh, g_aggh);
    cudaGetSymbolAddress(&paggl, g_aggl);
    cudaGetSymbolAddress(&presh, g_resh);
    cudaGetSymbolAddress(&presl, g_resl);

    // 1: Wf = Wq@Wak, bf, counter resets
    wcomb1<<<dim3(2, 4), 256>>>(Wq, Wak, bq);
    // 2: Wf2 = Wf@Wkl^T, bf2, e, c
    wcomb2<<<dim3(2, 4), 256>>>(Wkl, bkl);
    // 3: presplit x + 18 weight matrices (+ zero softmax state + scatter)
    {
        long long total = (long long)ND + (long long)NW * MSZ;
        k_splitall<<<(unsigned)((total + 255) / 256), 256>>>(
            meta_xs, q_w, k_w, v_w, a_w, WMk, node_type);
    }

    dim3 gT((NN + 127) / 128, TT);
    dim3 gK((NN + 127) / 128, KKM);
    __half* xh = (__half*)pxh; __half* xl = (__half*)pxl;

    // 4: merged q/k/v/front2 GEMM (typed; shares gathered A)  <-- profiled slot
    {
        GMArgs a;
        a.n = 6;
        a.s[0] = { 0, 1, q_b, 1, (float*)pq, 0 };
        a.s[1] = { 3, 1, k_b, 1, (float*)pk, 0 };
        a.s[2] = { 6, 1, v_b, 1, (float*)pv, 0 };
        a.s[3] = { 15, 0, (const float*)pbf2,          0, (float*)pfront2, 0 };
        a.s[4] = { 16, 0, (const float*)pbf2 + DD,     0, (float*)pfront2 + (long long)ND, 0 };
        a.s[5] = { 17, 0, (const float*)pbf2 + 2 * DD, 0, (float*)pfront2 + 2LL * ND, 0 };
        tc_gemm_ms<<<gT, 256, GSM_MS>>>(xh, xl, 0, 1, 0, a);
    }

    // 5-7: edge pipeline
    k_qA<<<592, 256, 81920>>>(rel_att);
    k_logits<<<2368, 256>>>(edge_idx, edge_type, rel_pri);
    k_msg<<<592, 256, 81920>>>(rel_msg, edge_idx, edge_type);

    // 8: aggm GEMM (gy = moment k)
    {
        GMArgs a;
        a.n = 1;
        a.s[0] = { 12, 1, nullptr, 0, (float*)paggm, (long long)ND };
        tc_gemm_ms<<<gK, 256, GSM_MS>>>((__half*)paggh, (__half*)paggl, (long long)ND, 0, NN, a);
    }

    // 9: gating -> split(gelu(res))
    k_gate<<<(NN * 32 + 255) / 256, 256>>>(meta_xs);

    // 10: trans = typed a_w GEMM over split(gelu(res))
    {
        GMArgs a;
        a.n = 1;
        a.s[0] = { 9, 1, a_b, 1, (float*)ptrans, 0 };
        tc_gemm_ms<<<gT, 256, GSM_MS>>>((__half*)presh, (__half*)presl, 0, 1, 0, a);
    }

    // 11: skip blend + LayerNorm
    k_postln<<<(NN * 32 + 255) / 256, 256>>>(node_type, meta_xs, skip, lng, lnb, out);
}

// round 14
// speedup vs baseline: 1.1130x; 1.1130x over previous
#include <cuda_runtime.h>
#include <cuda_fp16.h>
#include <math.h>
#include <stdint.h>

#define NN 40000
#define EE 320000
#define DD 128
#define HH 4
#define TT 3
#define RR 5
#define KKM 3
#define DKK 32
#define ND (NN*DD)
#define MSZ (DD*DD)
#define NPART 157
#define INV_SQRT_DK 0.17677669529663687f   // 1/sqrt(32)

// GEMM smem (bytes): A full-K 128 rows x 272B x 2 planes at 0 / 34816.
// B: double-buffered 32-k stages: buf b at 69632 + b*17408, planes +8704.
#define M_AL 34816
#define M_B  69632
#define GSM_MS 104448
#define NW 18   // slots: 0-2 qw, 3-5 kw, 6-8 vw, 9-11 aw, 12-14 WMk, 15-17 Wf2

// wcomb_fused smem
#define WPITCH 132
#define WSM_FLOATS (128*WPITCH + 32*WPITCH + 128 + 32)
#define WSM_BYTES (WSM_FLOATS*4)

// ---------------- scratch (device globals; no allocation allowed) -------------
__device__ float    g_q[ND];
__device__ float    g_v[ND];
__device__ __half   g_kh[ND];                 // k projection, fp16
__device__ __half   g_qAh[NN*RR*DD];          // rel_att-transformed q, fp16
__device__ float    g_logits[EE*HH];          // exp(logit)
__device__ float    g_sum[NN*HH];
__device__ int      g_deg[NN];
__device__ float    g_aggm[KKM*ND];
__device__ float    g_front2[KKM*ND];         // x @ Wf2_k + bf2_k
__device__ float    g_trans[ND];
__device__ float    g_Wf2[KKM*MSZ];           // Wq@Wak[k]@Wkl^T (fp32 exact)
__device__ float    g_bf2[KKM*DD];            // (bq@Wak[k]) @ Wkl^T
__device__ float    g_e[KKM*DD];              // (Wq@Wak[k]) @ bkl
__device__ float    g_c[KKM];                 // (bq@Wak[k]) . bkl
// presplit half planes
__device__ __half   g_xh[ND],        g_xl[ND];
__device__ __half   g_aggh[KKM*ND],  g_aggl[KKM*ND];
__device__ __half   g_resh[ND],      g_resl[ND];
__device__ __half   g_w2[NW*2*MSZ];           // weights: slot*2*MSZ, hi then lo
__device__ int      g_list[TT*NN];
__device__ int      g_cnt[TT];
__device__ int      g_cur[TT];

// ---------------- helpers ----------------
__device__ __forceinline__ float signed_cbrt(float a) {
    float s = (a > 0.f) ? 1.f : ((a < 0.f) ? -1.f : 0.f);
    return s * cbrtf(fabsf(a) + 1e-18f);
}
__device__ __forceinline__ float gelu_exact(float x) {
    return 0.5f * x * (1.f + erff(x * 0.70710678118654752440f));
}
__device__ __forceinline__ float warp_sum(float p) {
    #pragma unroll
    for (int o = 16; o > 0; o >>= 1) p += __shfl_xor_sync(0xffffffffu, p, o);
    return p;
}
__device__ __forceinline__ void splith(float x, __half& hi, __half& lo) {
    __half h = __float2half_rn(x);
    hi = h;
    lo = __float2half_rn(x - __half2float(h));
}
__device__ __forceinline__ uint32_t smem_u32(const void* p) {
    uint32_t a;
    asm("{ .reg .u64 t; cvta.to.shared.u64 t, %1; cvt.u32.u64 %0, t; }" : "=r"(a) : "l"(p));
    return a;
}

#define CPA16(dst, src, sz)                                                   \
    asm volatile("cp.async.ca.shared.global [%0], [%1], 16, %2;"              \
        :: "r"(dst), "l"(src), "r"(sz))
#define CPA_COMMIT() asm volatile("cp.async.commit_group;" ::: "memory")
#define CPA_WAIT1()  asm volatile("cp.async.wait_group 1;" ::: "memory")
#define LDSM4(r, addr)                                                        \
    asm volatile("ldmatrix.sync.aligned.m8n8.x4.shared.b16 {%0,%1,%2,%3}, [%4];" \
        : "=r"((r)[0]), "=r"((r)[1]), "=r"((r)[2]), "=r"((r)[3]) : "r"(addr))
#define LDSM4T(r, addr)                                                       \
    asm volatile("ldmatrix.sync.aligned.m8n8.x4.trans.shared.b16 {%0,%1,%2,%3}, [%4];" \
        : "=r"((r)[0]), "=r"((r)[1]), "=r"((r)[2]), "=r"((r)[3]) : "r"(addr))
#define MMA16(acc, a, b0, b1)                                                 \
    asm volatile("mma.sync.aligned.m16n8k16.row.col.f32.f16.f16.f32 "         \
        "{%0,%1,%2,%3}, {%4,%5,%6,%7}, {%8,%9}, {%0,%1,%2,%3};"               \
        : "+f"((acc)[0]), "+f"((acc)[1]), "+f"((acc)[2]), "+f"((acc)[3])      \
        : "r"((a)[0]), "r"((a)[1]), "r"((a)[2]), "r"((a)[3]), "r"(b0), "r"(b1))

// ---------------- counter reset (launch 1) -----------------------------------
__global__ void k_reset() {
    if (threadIdx.x < TT) {
        g_cnt[threadIdx.x] = 0;
        g_cur[threadIdx.x] = threadIdx.x * NN;
    }
}

// ------ fused weight combine (launch 2): grid (4, KKM) ------------------------
// Per block: rows rbase..rbase+32 of: T = Wq@Wak[k]; Wf2 = T@Wkl^T; e = T@bkl.
// Block x==0 extra: bf = bq@Wak[k]; bf2 = bf@Wkl^T; c = bf.bkl.
__global__ __launch_bounds__(256) void wcomb_fused(
    const float* __restrict__ Wq, const float* __restrict__ Wak,
    const float* __restrict__ Wkl, const float* __restrict__ bq,
    const float* __restrict__ bkl)
{
    extern __shared__ float ws[];
    float* Bs   = ws;                           // 128 x WPITCH
    float* Ts   = ws + 128 * WPITCH;            // 32 x WPITCH
    float* bfS  = Ts + 32 * WPITCH;             // 128
    float* esum = bfS + 128;                    // 32
    int k = blockIdx.y, xb = blockIdx.x;
    int tid = threadIdx.x;
    int rloc = tid >> 3;            // 0..31
    int cg = tid & 7;               // 0..7
    int rbase = xb * 32;

    // stage1: Bs = Wak[k]
    for (int i = tid; i < 128 * 32; i += 256) {
        int d = i >> 5, c4 = (i & 31) << 2;
        *(float4*)&Bs[d * WPITCH + c4] =
            *(const float4*)(Wak + (long long)k * MSZ + (long long)d * DD + c4);
    }
    if (tid < 32) esum[tid] = 0.f;
    __syncthreads();

    const float* wqr = Wq + (long long)(rbase + rloc) * DD;
    float T[16];
    #pragma unroll
    for (int i = 0; i < 16; i++) T[i] = 0.f;
    for (int d = 0; d < 128; d++) {
        float a = wqr[d];
        const float* bd = Bs + d * WPITCH + cg;
        #pragma unroll
        for (int i = 0; i < 16; i++) T[i] += a * bd[i * 8];
    }
    float ep = 0.f;
    #pragma unroll
    for (int i = 0; i < 16; i++) {
        int c = cg + i * 8;
        Ts[rloc * WPITCH + c] = T[i];
        ep += T[i] * bkl[c];
    }
    atomicAdd(&esum[rloc], ep);
    if (xb == 0 && tid < 128) {
        float s = 0.f;
        for (int d = 0; d < 128; d++) s += bq[d] * Bs[d * WPITCH + tid];
        bfS[tid] = s;
    }
    __syncthreads();
    if (tid < 32) g_e[k * DD + rbase + tid] = esum[tid];

    // stage2: Bs = Wkl
    for (int i = tid; i < 128 * 32; i += 256) {
        int d = i >> 5, c4 = (i & 31) << 2;
        *(float4*)&Bs[d * WPITCH + c4] = *(const float4*)(Wkl + (long long)d * DD + c4);
    }
    __syncthreads();

    const float* tsr = Ts + rloc * WPITCH;
    for (int i = 0; i < 16; i++) {
        int d2 = cg + i * 8;
        const float* bd = Bs + d2 * WPITCH;
        float s = 0.f;
        for (int j = 0; j < 128; j += 4) {
            float4 t4 = *(const float4*)&tsr[j];
            float4 b4 = *(const float4*)&bd[j];
            s += t4.x * b4.x + t4.y * b4.y + t4.z * b4.z + t4.w * b4.w;
        }
        g_Wf2[(long long)k * MSZ + (long long)(rbase + rloc) * DD + d2] = s;
    }
    if (xb == 0 && tid < 128) {
        const float* bd = Bs + tid * WPITCH;
        float s = 0.f;
        for (int n = 0; n < 128; n++) s += bfS[n] * bd[n];
        g_bf2[k * DD + tid] = s;
    }
    if (xb == 0 && tid == 0) {
        float s = 0.f;
        for (int n = 0; n < 128; n++) s += bfS[n] * bkl[n];
        g_c[k] = s;
    }
}

// ------- presplit everything + zero softmax state + fused scatter (launch 3) -
__global__ void k_splitall(const float* __restrict__ x,
                           const float* __restrict__ qw, const float* __restrict__ kw,
                           const float* __restrict__ vw, const float* __restrict__ aw,
                           const float* __restrict__ WMk, const int* __restrict__ nt) {
    if (blockIdx.x < NPART) {
        __shared__ int h[TT], base[TT];
        if (threadIdx.x < TT) h[threadIdx.x] = 0;
        __syncthreads();
        int n = blockIdx.x * blockDim.x + threadIdx.x;
        int t = 0, loc = 0;
        bool v = (n < NN);
        if (v) { t = nt[n]; loc = atomicAdd(&h[t], 1); }
        __syncthreads();
        if (threadIdx.x < TT && h[threadIdx.x]) {
            base[threadIdx.x] = atomicAdd(&g_cur[threadIdx.x], h[threadIdx.x]);
            atomicAdd(&g_cnt[threadIdx.x], h[threadIdx.x]);
        }
        __syncthreads();
        if (v) g_list[base[t] + loc] = n;
    }

    long long total = (long long)ND + (long long)NW * MSZ;
    long long i = (long long)blockIdx.x * blockDim.x + threadIdx.x;
    if (i >= total) return;
    if (i < NN * HH) g_sum[i] = 0.f;
    if (i < NN) g_deg[i] = 0;
    float s;
    __half h, l;
    if (i < ND) {
        s = x[i];
        splith(s, h, l);
        g_xh[i] = h; g_xl[i] = l;
    } else {
        long long wi = i - ND;
        if      (wi <  3LL * MSZ) s = qw[wi];
        else if (wi <  6LL * MSZ) s = kw[wi - 3LL * MSZ];
        else if (wi <  9LL * MSZ) s = vw[wi - 6LL * MSZ];
        else if (wi < 12LL * MSZ) s = aw[wi - 9LL * MSZ];
        else if (wi < 15LL * MSZ) s = WMk[wi - 12LL * MSZ];
        else                      s = g_Wf2[wi - 15LL * MSZ];
        splith(s, h, l);
        long long slot = wi >> 14;
        long long off  = wi & (MSZ - 1);
        g_w2[slot * 2 * MSZ + off] = h;
        g_w2[slot * 2 * MSZ + MSZ + off] = l;
    }
}

// ------ multi-set fp16-split tensor GEMM ------------------------------------
struct GMSet {
    int wslot;
    int waddgy;
    const float* bias;
    int baddgy;
    void* out;
    long long ogys;
    int outhalf;
};
struct GMArgs { GMSet s[6]; int n; };

__global__ __launch_bounds__(256, 2) void tc_gemm_ms(
    const __half* __restrict__ Xh, const __half* __restrict__ Xl, long long xgys,
    int typed, int nrows, GMArgs args)
{
    extern __shared__ char smc[];
    uint32_t sb = smem_u32(smc);

    int gy = blockIdx.y;
    const int* rows = nullptr;
    int cnt;
    if (typed) {
        rows = g_list + (long long)gy * NN;
        cnt = g_cnt[gy];
    } else {
        Xh += (long long)gy * xgys;
        Xl += (long long)gy * xgys;
        cnt = nrows;
    }
    int bm = blockIdx.x * 128;
    if (bm >= cnt) return;

    int tid = threadIdx.x, wid = tid >> 5, lane = tid & 31;
    int warpM = wid & 3, warpN = wid >> 2;
    int rbase = warpM * 32, cbase = warpN * 64;
    int qid = lane >> 2, tq = lane & 3;

    int li = lane & 7, ls = lane >> 3;
    int a_row = li + ((ls & 1) << 3);
    int a_col = ((ls >> 1) & 1) << 3;
    int b_krow = li + ((ls >> 1) << 3);
    int b_ncol = (ls & 1) << 3;

    uint32_t aoff = sb + (uint32_t)(rbase + a_row) * 272u + (uint32_t)a_col * 2u;
    uint32_t bfrag = (uint32_t)b_krow * 272u + (uint32_t)(cbase + b_ncol) * 2u;

    int bSrc[4]; uint32_t bDst[4];
    #pragma unroll
    for (int it = 0; it < 4; it++) {
        int s = tid + it * 256;
        int plane = s >> 9, rc = s & 511;
        int k = rc >> 4, c16 = rc & 15;
        bSrc[it] = plane * MSZ + k * DD + c16 * 8;
        bDst[it] = (uint32_t)(plane * 8704 + k * 272 + c16 * 16);
    }
    uint32_t bB0 = sb + M_B, bB1 = sb + M_B + 17408u;

    // stage full-K A (once)
    #pragma unroll
    for (int it = 0; it < 16; it++) {
        int s = tid + it * 256;
        int plane = s >> 11, rc = s & 2047;
        int r = rc >> 4, c16 = rc & 15;
        int gr = bm + r;
        int row = (gr < cnt) ? (rows ? rows[gr] : gr) : 0;
        unsigned sz = (gr < cnt) ? 16u : 0u;
        const __half* srcp = (plane ? Xl : Xh) + (long long)row * DD + c16 * 8;
        uint32_t dst = sb + (plane ? M_AL : 0) + (uint32_t)r * 272u + (uint32_t)c16 * 16u;
        CPA16(dst, srcp, sz);
    }
    {
        int slot0 = args.s[0].wslot + (args.s[0].waddgy ? gy : 0);
        const __half* wb = g_w2 + (long long)slot0 * (2 * MSZ);
        #pragma unroll
        for (int it = 0; it < 4; it++) CPA16(bB0 + bDst[it], wb + bSrc[it], 16u);
    }
    CPA_COMMIT();

    int gst = 0;
    int nstages = args.n * 4;

    for (int si = 0; si < args.n; si++) {
        float acc[2][8][4];
        #pragma unroll
        for (int mi = 0; mi < 2; mi++)
            #pragma unroll
            for (int ni = 0; ni < 8; ni++)
                #pragma unroll
                for (int j = 0; j < 4; j++) acc[mi][ni][j] = 0.f;

        for (int st = 0; st < 4; st++) {
            int nb = gst + 1;
            if (nb < nstages) {
                int nsi = nb >> 2, nst = nb & 3;
                int nslot = args.s[nsi].wslot + (args.s[nsi].waddgy ? gy : 0);
                const __half* wb = g_w2 + (long long)nslot * (2 * MSZ) + nst * (32 * DD);
                uint32_t bb = (nb & 1) ? bB1 : bB0;
                #pragma unroll
                for (int it = 0; it < 4; it++) CPA16(bb + bDst[it], wb + bSrc[it], 16u);
            }
            CPA_COMMIT();
            CPA_WAIT1();
            __syncthreads();

            uint32_t bbase = (gst & 1) ? bB1 : bB0;
            #pragma unroll
            for (int k16 = 0; k16 < 2; k16++) {
                uint32_t ka = aoff + (uint32_t)(st * 64 + k16 * 32);
                uint32_t ah[2][4], al[2][4];
                LDSM4(ah[0], ka);
                LDSM4(ah[1], ka + 16u * 272u);
                LDSM4(al[0], ka + (uint32_t)M_AL);
                LDSM4(al[1], ka + (uint32_t)M_AL + 16u * 272u);
                #pragma unroll
                for (int nf = 0; nf < 4; nf++) {
                    uint32_t kb = bbase + bfrag + (uint32_t)k16 * 4352u + (uint32_t)nf * 32u;
                    uint32_t bhf[4], blf[4];
                    LDSM4T(bhf, kb);
                    LDSM4T(blf, kb + 8704u);
                    #pragma unroll
                    for (int j = 0; j < 2; j++) {
                        #pragma unroll
                        for (int mi = 0; mi < 2; mi++) {
                            float* a4 = acc[mi][nf * 2 + j];
                            MMA16(a4, ah[mi], bhf[j], bhf[2 + j]);
                            MMA16(a4, al[mi], bhf[j], bhf[2 + j]);
                            MMA16(a4, ah[mi], blf[j], blf[2 + j]);
                        }
                    }
                }
            }
            __syncthreads();
            gst++;
        }

        const GMSet& st_ = args.s[si];
        const float* bp = st_.bias;
        if (bp && st_.baddgy) bp += (long long)gy * DD;
        if (st_.outhalf) {
            __half* op = (__half*)st_.out + (long long)gy * st_.ogys;
            #pragma unroll
            for (int ni = 0; ni < 8; ni++) {
                int col = cbase + ni * 8 + tq * 2;
                float bx = bp ? __ldg(bp + col) : 0.f;
                float by = bp ? __ldg(bp + col + 1) : 0.f;
                #pragma unroll
                for (int mi = 0; mi < 2; mi++) {
                    int r0 = bm + rbase + mi * 16 + qid;
                    if (r0 < cnt) {
                        int row = rows ? rows[r0] : r0;
                        *(__half2*)(op + (long long)row * DD + col) =
                            __floats2half2_rn(acc[mi][ni][0] + bx, acc[mi][ni][1] + by);
                    }
                    int r1 = r0 + 8;
                    if (r1 < cnt) {
                        int row = rows ? rows[r1] : r1;
                        *(__half2*)(op + (long long)row * DD + col) =
                            __floats2half2_rn(acc[mi][ni][2] + bx, acc[mi][ni][3] + by);
                    }
                }
            }
        } else {
            float* op = (float*)st_.out + (long long)gy * st_.ogys;
            #pragma unroll
            for (int ni = 0; ni < 8; ni++) {
                int col = cbase + ni * 8 + tq * 2;
                float bx = bp ? __ldg(bp + col) : 0.f;
                float by = bp ? __ldg(bp + col + 1) : 0.f;
                #pragma unroll
                for (int mi = 0; mi < 2; mi++) {
                    int r0 = bm + rbase + mi * 16 + qid;
                    if (r0 < cnt) {
                        int row = rows ? rows[r0] : r0;
                        float2 o = make_float2(acc[mi][ni][0] + bx, acc[mi][ni][1] + by);
                        *(float2*)(op + (long long)row * DD + col) = o;
                    }
                    int r1 = r0 + 8;
                    if (r1 < cnt) {
                        int row = rows ? rows[r1] : r1;
                        float2 o = make_float2(acc[mi][ni][2] + bx, acc[mi][ni][3] + by);
                        *(float2*)(op + (long long)row * DD + col) = o;
                    }
                }
            }
        }
    }
}

// ---------------- qA = rel_att-transformed q -> fp16 ---------------------------
__global__ void k_qA(const float* __restrict__ rel_att) {
    extern __shared__ float Ashm[];
    for (int i = threadIdx.x; i < RR * HH * DKK * DKK; i += blockDim.x) {
        int rh = i >> 10, dm = i & 1023, d = dm >> 5, m = dm & 31;
        Ashm[(rh * 32 + m) * 32 + d] = rel_att[i];
    }
    __syncthreads();
    int lane = threadIdx.x & 31;
    int gw = (blockIdx.x * blockDim.x + threadIdx.x) >> 5;
    int nw = (gridDim.x * blockDim.x) >> 5;
    for (int n = gw; n < NN; n += nw) {
        float qr[HH];
        #pragma unroll
        for (int h = 0; h < HH; h++) qr[h] = g_q[n * DD + h * 32 + lane];
        #pragma unroll
        for (int h = 0; h < HH; h++) {
            float a0 = 0, a1 = 0, a2 = 0, a3 = 0, a4 = 0;
            #pragma unroll
            for (int m = 0; m < 32; m++) {
                float qm = __shfl_sync(0xffffffffu, qr[h], m);
                int base = (h * 32 + m) * 32 + lane;
                a0 += Ashm[base        ] * qm;
                a1 += Ashm[base +  4096] * qm;
                a2 += Ashm[base +  8192] * qm;
                a3 += Ashm[base + 12288] * qm;
                a4 += Ashm[base + 16384] * qm;
            }
            long long nb = (long long)n * RR * DD + h * 32 + lane;
            g_qAh[nb           ] = __float2half_rn(a0);
            g_qAh[nb +     DD  ] = __float2half_rn(a1);
            g_qAh[nb + 2 * DD  ] = __float2half_rn(a2);
            g_qAh[nb + 3 * DD  ] = __float2half_rn(a3);
            g_qAh[nb + 4 * DD  ] = __float2half_rn(a4);
        }
    }
}

// ---- edge logits (fp16 operands) + fused exp + segment sum + degree ---------
__global__ void k_logits(const int* __restrict__ ei, const int* __restrict__ et,
                         const float* __restrict__ rel_pri) {
    int lane = threadIdx.x & 31;
    int gw = (blockIdx.x * blockDim.x + threadIdx.x) >> 5;
    int nw = (gridDim.x * blockDim.x) >> 5;
    for (int e = gw; e < EE; e += nw) {
        int s = ei[e], tg = ei[EE + e], r = et[e];
        const __half* kb = g_kh + (long long)s * DD + lane * 4;
        const __half* qa = g_qAh + ((long long)tg * RR + r) * DD + lane * 4;
        __half2 k0 = *(const __half2*)kb;
        __half2 k1 = *(const __half2*)(kb + 2);
        __half2 q0 = *(const __half2*)qa;
        __half2 q1 = *(const __half2*)(qa + 2);
        float2 kf0 = __half22float2(k0), kf1 = __half22float2(k1);
        float2 qf0 = __half22float2(q0), qf1 = __half22float2(q1);
        float p = kf0.x * qf0.x + kf0.y * qf0.y + kf1.x * qf1.x + kf1.y * qf1.y;
        p += __shfl_xor_sync(0xffffffffu, p, 1);
        p += __shfl_xor_sync(0xffffffffu, p, 2);
        p += __shfl_xor_sync(0xffffffffu, p, 4);
        if ((lane & 7) == 0) {
            int h = lane >> 3;
            float ev = expf(p * rel_pri[r * HH + h] * INV_SQRT_DK);
            g_logits[e * HH + h] = ev;
            atomicAdd(&g_sum[tg * HH + h], ev);
        }
        if (lane == 0) atomicAdd(&g_deg[tg], 1);
    }
}

// ------- messages / agg (edge n < N shortcut); writes SPLIT halves -----------
__global__ void k_msg(const float* __restrict__ rel_msg, const int* __restrict__ ei,
                      const int* __restrict__ et) {
    extern __shared__ float Ms[];
    for (int i = threadIdx.x; i < RR * HH * DKK * DKK; i += blockDim.x) Ms[i] = rel_msg[i];
    __syncthreads();
    int lane = threadIdx.x & 31;
    int gw = (blockIdx.x * blockDim.x + threadIdx.x) >> 5;
    int nw = (gridDim.x * blockDim.x) >> 5;
    for (int n = gw; n < NN; n += nw) {
        int s = ei[n], tg = ei[EE + n], r = et[n];
        float deg = (float)g_deg[n];
        float vr[HH];
        #pragma unroll
        for (int h = 0; h < HH; h++) vr[h] = g_v[(long long)s * DD + h * 32 + lane];
        #pragma unroll
        for (int h = 0; h < HH; h++) {
            float att = g_logits[n * HH + h] / (g_sum[tg * HH + h] + 1e-16f);
            float vp = 0.f;
            const float* Mb = Ms + (r * HH + h) * 1024;
            #pragma unroll
            for (int d = 0; d < 32; d++) {
                float vd = __shfl_sync(0xffffffffu, vr[h], d);
                vp += Mb[d * 32 + lane] * vd;
            }
            float base = deg * att;
            int o = n * DD + h * 32 + lane;
            float vp2 = vp * vp;
            float m1 = base * vp;
            float m2 = base * vp2;
            float m3 = signed_cbrt(base * vp2 * vp);
            __half hh, ll;
            splith(m1, hh, ll); g_aggh[o] = hh;          g_aggl[o] = ll;
            splith(m2, hh, ll); g_aggh[ND + o] = hh;     g_aggl[ND + o] = ll;
            splith(m3, hh, ll); g_aggh[2 * ND + o] = hh; g_aggl[2 * ND + o] = ll;
        }
    }
}

// -- gate = sigmoid(dot(front2,aggm) + dot(e_k,x) + c_k); res += gate*aggm ----
__global__ void k_gate(const float* __restrict__ x) {
    int w = (blockIdx.x * blockDim.x + threadIdx.x) >> 5;
    int lane = threadIdx.x & 31;
    if (w >= NN) return;
    int o = w * DD + lane * 4;
    float4 xv = *(const float4*)(x + o);
    float4 r4 = make_float4(0.f, 0.f, 0.f, 0.f);
    #pragma unroll
    for (int k = 0; k < KKM; k++) {
        float4 f = *(float4*)&g_front2[k * ND + o];
        float4 a = *(float4*)&g_aggm[k * ND + o];
        float4 ek = *(const float4*)&g_e[k * DD + lane * 4];
        float p = f.x * a.x + f.y * a.y + f.z * a.z + f.w * a.w
                + ek.x * xv.x + ek.y * xv.y + ek.z * xv.z + ek.w * xv.w;
        p = warp_sum(p);
        float gate = 1.f / (1.f + expf(-(p + g_c[k])));
        r4.x += gate * a.x; r4.y += gate * a.y; r4.z += gate * a.z; r4.w += gate * a.w;
    }
    float y0 = gelu_exact(r4.x), y1 = gelu_exact(r4.y);
    float y2 = gelu_exact(r4.z), y3 = gelu_exact(r4.w);
    __half h0, h1, h2, h3, l0, l1, l2, l3;
    splith(y0, h0, l0); splith(y1, h1, l1);
    splith(y2, h2, l2); splith(y3, h3, l3);
    *(__half2*)&g_resh[o]     = __halves2half2(h0, h1);
    *(__half2*)&g_resh[o + 2] = __halves2half2(h2, h3);
    *(__half2*)&g_resl[o]     = __halves2half2(l0, l1);
    *(__half2*)&g_resl[o + 2] = __halves2half2(l2, l3);
}

// ---------------- skip blend + LayerNorm --------------------------------------
__global__ void k_postln(const int* __restrict__ nt, const float* __restrict__ xin,
                         const float* __restrict__ skip, const float* __restrict__ lng,
                         const float* __restrict__ lnb, float* __restrict__ out) {
    int wid = (blockIdx.x * blockDim.x + threadIdx.x) >> 5;
    int lane = threadIdx.x & 31;
    if (wid >= NN) return;
    int t = nt[wid];
    float alpha = 1.f / (1.f + expf(-skip[t]));
    int o = wid * DD + lane * 4;
    float4 tr = *(float4*)&g_trans[o];
    float4 xv = *(const float4*)(xin + o);
    float y0 = tr.x * alpha + xv.x * (1.f - alpha);
    float y1 = tr.y * alpha + xv.y * (1.f - alpha);
    float y2 = tr.z * alpha + xv.z * (1.f - alpha);
    float y3 = tr.w * alpha + xv.w * (1.f - alpha);
    float s  = y0 + y1 + y2 + y3;
    float ss = y0 * y0 + y1 * y1 + y2 * y2 + y3 * y3;
    #pragma unroll
    for (int of = 16; of > 0; of >>= 1) {
        s  += __shfl_xor_sync(0xffffffffu, s,  of);
        ss += __shfl_xor_sync(0xffffffffu, ss, of);
    }
    float mu  = s * (1.f / 128.f);
    float inv = rsqrtf(ss * (1.f / 128.f) - mu * mu + 1e-5f);
    float4 gg = *(const float4*)(lng + t * DD + lane * 4);
    float4 bb = *(const float4*)(lnb + t * DD + lane * 4);
    float4 o4;
    o4.x = (y0 - mu) * inv * gg.x + bb.x;
    o4.y = (y1 - mu) * inv * gg.y + bb.y;
    o4.z = (y2 - mu) * inv * gg.z + bb.z;
    o4.w = (y3 - mu) * inv * gg.w + bb.w;
    *(float4*)(out + (long long)wid * DD + lane * 4) = o4;
}

// ---------------- launch ----------------
extern "C" void kernel_launch(void* const* d_in, const int* in_sizes, int n_in,
                              void* d_out, int out_size) {
    const float* meta_xs  = (const float*)d_in[0];
    const int*   node_type= (const int*)  d_in[1];
    const int*   edge_idx = (const int*)  d_in[2];
    const int*   edge_type= (const int*)  d_in[3];
    const float* q_w = (const float*)d_in[5],  *q_b = (const float*)d_in[6];
    const float* k_w = (const float*)d_in[7],  *k_b = (const float*)d_in[8];
    const float* v_w = (const float*)d_in[9],  *v_b = (const float*)d_in[10];
    const float* a_w = (const float*)d_in[11], *a_b = (const float*)d_in[12];
    const float* rel_pri = (const float*)d_in[13];
    const float* rel_att = (const float*)d_in[14];
    const float* rel_msg = (const float*)d_in[15];
    const float* WMk = (const float*)d_in[16];
    const float* Wak = (const float*)d_in[17];
    const float* Wq  = (const float*)d_in[18], *bq  = (const float*)d_in[19];
    const float* Wkl = (const float*)d_in[20], *bkl = (const float*)d_in[21];
    const float* skip= (const float*)d_in[22];
    const float* lng = (const float*)d_in[23], *lnb = (const float*)d_in[24];
    float* out = (float*)d_out;

    cudaFuncSetAttribute(k_qA,        cudaFuncAttributeMaxDynamicSharedMemorySize, 81920);
    cudaFuncSetAttribute(k_msg,       cudaFuncAttributeMaxDynamicSharedMemorySize, 81920);
    cudaFuncSetAttribute(tc_gemm_ms,  cudaFuncAttributeMaxDynamicSharedMemorySize, GSM_MS);
    cudaFuncSetAttribute(wcomb_fused, cudaFuncAttributeMaxDynamicSharedMemorySize, WSM_BYTES);

    void *pq, *pkh, *pv, *paggm, *pfront2, *ptrans, *pbf2;
    void *pxh, *pxl, *paggh, *paggl, *presh, *presl;
    cudaGetSymbolAddress(&pq, g_q);
    cudaGetSymbolAddress(&pkh, g_kh);
    cudaGetSymbolAddress(&pv, g_v);
    cudaGetSymbolAddress(&paggm, g_aggm);
    cudaGetSymbolAddress(&pfront2, g_front2);
    cudaGetSymbolAddress(&ptrans, g_trans);
    cudaGetSymbolAddress(&pbf2, g_bf2);
    cudaGetSymbolAddress(&pxh, g_xh);
    cudaGetSymbolAddress(&pxl, g_xl);
    cudaGetSymbolAddress(&paggh, g_aggh);
    cudaGetSymbolAddress(&paggl, g_aggl);
    cudaGetSymbolAddress(&presh, g_resh);
    cudaGetSymbolAddress(&presl, g_resl);

    // 1: counter resets
    k_reset<<<1, 32>>>();
    // 2: fused exact fp32 weight combines (Wf2, bf2, e, c)
    wcomb_fused<<<dim3(4, KKM), 256, WSM_BYTES>>>(Wq, Wak, Wkl, bq, bkl);
    // 3: presplit x + 18 weight matrices (+ zero softmax state + scatter)
    {
        long long total = (long long)ND + (long long)NW * MSZ;
        k_splitall<<<(unsigned)((total + 255) / 256), 256>>>(
            meta_xs, q_w, k_w, v_w, a_w, WMk, node_type);
    }

    dim3 gT((NN + 127) / 128, TT);
    dim3 gK((NN + 127) / 128, KKM);
    __half* xh = (__half*)pxh; __half* xl = (__half*)pxl;

    // 4: merged q/k/v/front2 GEMM (typed; k written fp16)  <-- profiled slot
    {
        GMArgs a;
        a.n = 6;
        a.s[0] = { 0, 1, q_b, 1, pq, 0, 0 };
        a.s[1] = { 3, 1, k_b, 1, pkh, 0, 1 };
        a.s[2] = { 6, 1, v_b, 1, pv, 0, 0 };
        a.s[3] = { 15, 0, (const float*)pbf2,          0, pfront2, 0, 0 };
        a.s[4] = { 16, 0, (const float*)pbf2 + DD,     0, (void*)((float*)pfront2 + (long long)ND), 0, 0 };
        a.s[5] = { 17, 0, (const float*)pbf2 + 2 * DD, 0, (void*)((float*)pfront2 + 2LL * ND), 0, 0 };
        tc_gemm_ms<<<gT, 256, GSM_MS>>>(xh, xl, 0, 1, 0, a);
    }

    // 5-7: edge pipeline (fp16 operands)
    k_qA<<<592, 256, 81920>>>(rel_att);
    k_logits<<<2368, 256>>>(edge_idx, edge_type, rel_pri);
    k_msg<<<592, 256, 81920>>>(rel_msg, edge_idx, edge_type);

    // 8: aggm GEMM (gy = moment k)
    {
        GMArgs a;
        a.n = 1;
        a.s[0] = { 12, 1, nullptr, 0, paggm, (long long)ND, 0 };
        tc_gemm_ms<<<gK, 256, GSM_MS>>>((__half*)paggh, (__half*)paggl, (long long)ND, 0, NN, a);
    }

    // 9: gating -> split(gelu(res))
    k_gate<<<(NN * 32 + 255) / 256, 256>>>(meta_xs);

    // 10: trans = typed a_w GEMM over split(gelu(res))
    {
        GMArgs a;
        a.n = 1;
        a.s[0] = { 9, 1, a_b, 1, ptrans, 0, 0 };
        tc_gemm_ms<<<gT, 256, GSM_MS>>>((__half*)presh, (__half*)presl, 0, 1, 0, a);
    }

    // 11: skip blend + LayerNorm
    k_postln<<<(NN * 32 + 255) / 256, 256>>>(node_type, meta_xs, skip, lng, lnb, out);
}